// round 15
// baseline (speedup 1.0000x reference)
#include <cuda_runtime.h>
#include <cuda_bf16.h>

// Fixed shapes per reference: B=4096 users, P=200 slots, tau=1.0
#define NB 4096
#define PMAX 200
#define PROWS 224
#define NTHREADS 256
#define TANH_WARPS 3       // warps 0..2: tanh path; warps 3..7: rcp path
#define ROWPAD_T -1.0e30f  // tanh row pad: tanh(-huge) = -1 -> term 0
#define COLPAD_T  1.0e30f  // tanh col pad
#define COLPAD_R  1.0e15f  // rcp col pad: q=1e30 finite, term -> 1 - q*rcp(q) ~ 0

// Scratch (no device allocation allowed -> __device__ globals)
__device__ float g_block_loss[NB];
__device__ unsigned int g_done_count = 0;

__device__ __forceinline__ float fast_tanh(float x) {
    float r;
    asm("tanh.approx.f32 %0, %1;" : "=f"(r) : "f"(x));
    return r;
}
__device__ __forceinline__ float fast_rcp(float x) {
    float r;
    asm("rcp.approx.f32 %0, %1;" : "=f"(r) : "f"(x));
    return r;
}

// ---- Path A (MUFU-heavy): sigmoid(p-n) = 0.5*tanh(ph-nh)+0.5, per pair
//      FADD + MUFU.TANH(rt~16) + FFMA. +0.5 baselines analytic.
template<int NC>
__device__ __forceinline__ float pair_sum_tanh(const float2* __restrict__ ph2,
                                               const float* __restrict__ neg_g,
                                               int p, int nIters, int tx, int wy)
{
    float nh[NC];
    #pragma unroll
    for (int c = 0; c < NC; c++) {
        int j = c * 32 + tx;
        nh[c] = (j < p) ? (0.5f * neg_g[j]) : COLPAD_T;
    }
    float acc0 = 0.0f, acc1 = 0.0f;
    for (int r = 0; r < nIters; r++) {
        float2 e01 = ph2[r * 8 + wy];        // row pair k = 8r+wy
        const float e0 = e01.x, e1 = e01.y;
        #pragma unroll
        for (int c = 0; c < NC; c++) {
            acc0 = fmaf(0.5f, fast_tanh(e0 - nh[c]), acc0);
            acc1 = fmaf(0.5f, fast_tanh(e1 - nh[c]), acc1);
        }
    }
    return acc0 + acc1 + (float)(nIters * NC);
}

// ---- Path B (fma-heavy, MUFU-light): with E=exp(pos), N=exp(neg),
//      e/(e+n0)+e/(e+n1) = 1 + (e^2 - q)*rcp(e^2 + e*m + q), m=n0+n1, q=n0*n1
//      per 2 pairs: FADD + FFMA + FFMA + MUFU.RCP(rt8) + FFMA.
//      Zero-padded rows (E=0) -> term ~0; COLPAD_R cols -> term ~0;
//      mixed pad reduces to the single real sigmoid (validated r9/r11).
template<int NC64>
__device__ __forceinline__ float pair_sum_rcp(const float2* __restrict__ e2,
                                              const float* __restrict__ neg_g,
                                              int p, int nIters, int tx, int wy)
{
    float m[NC64], q[NC64];
    #pragma unroll
    for (int c = 0; c < NC64; c++) {
        int j0 = c * 64 + 2 * tx;
        float n0 = (j0     < p) ? __expf(neg_g[j0])     : COLPAD_R;
        float n1 = (j0 + 1 < p) ? __expf(neg_g[j0 + 1]) : COLPAD_R;
        m[c] = n0 + n1;
        q[c] = n0 * n1;
    }
    float acc0 = 0.0f, acc1 = 0.0f;
    for (int r = 0; r < nIters; r++) {
        float2 e01 = e2[r * 8 + wy];         // row pair k = 8r+wy
        const float e0 = e01.x, e1 = e01.y;
        #pragma unroll
        for (int c = 0; c < NC64; c++) {
            float u0 = e0 + m[c];
            float u1 = e1 + m[c];
            float d0 = fmaf(e0, u0, q[c]);
            float d1 = fmaf(e1, u1, q[c]);
            float g0 = fmaf(e0, e0, -q[c]);
            float g1 = fmaf(e1, e1, -q[c]);
            acc0 = fmaf(g0, fast_rcp(d0), acc0);
            acc1 = fmaf(g1, fast_rcp(d1), acc1);
        }
    }
    return acc0 + acc1 + (float)(2 * nIters * NC64);
}

__global__ __launch_bounds__(NTHREADS, 7) void sauc_kernel(
    const float* __restrict__ scores_pos,
    const float* __restrict__ scores_neg,
    const int* __restrict__ pos_counts,
    float* __restrict__ out)
{
    const int b = blockIdx.x;
    const int tid = threadIdx.x;
    const int tx = tid & 31;
    const int wy = tid >> 5;
    const int p = pos_counts[b];

    __shared__ __align__(8) float s_ph[PROWS];    // pos/2 (tanh rows)
    __shared__ __align__(8) float s_epos[PROWS];  // exp(pos) (rcp rows), 0-pad
    __shared__ float s_warp[NTHREADS / 32];
    __shared__ unsigned int s_is_last;

    if (tid < PROWS) {
        if (tid < p) {
            float v = scores_pos[b * PMAX + tid];
            s_ph[tid]   = 0.5f * v;
            s_epos[tid] = __expf(v);
        } else {
            s_ph[tid]   = ROWPAD_T;
            s_epos[tid] = 0.0f;
        }
    }
    __syncthreads();

    const float* neg_g = scores_neg + b * PMAX;
    const int kpairs = (p + 1) >> 1;           // row pairs
    const int dk = kpairs - wy;
    const int nIters = (dk > 0) ? ((dk + 7) >> 3) : 0;   // warp-uniform

    float acc;
    if (wy < TANH_WARPS) {
        const float2* ph2 = (const float2*)s_ph;
        const int nc = (p + 31) >> 5;          // 1..7
        switch (nc) {
            case 1:  acc = pair_sum_tanh<1>(ph2, neg_g, p, nIters, tx, wy); break;
            case 2:  acc = pair_sum_tanh<2>(ph2, neg_g, p, nIters, tx, wy); break;
            case 3:  acc = pair_sum_tanh<3>(ph2, neg_g, p, nIters, tx, wy); break;
            case 4:  acc = pair_sum_tanh<4>(ph2, neg_g, p, nIters, tx, wy); break;
            case 5:  acc = pair_sum_tanh<5>(ph2, neg_g, p, nIters, tx, wy); break;
            case 6:  acc = pair_sum_tanh<6>(ph2, neg_g, p, nIters, tx, wy); break;
            default: acc = pair_sum_tanh<7>(ph2, neg_g, p, nIters, tx, wy); break;
        }
    } else {
        const float2* e2 = (const float2*)s_epos;
        const int nc64 = (p + 63) >> 6;        // 1..4
        switch (nc64) {
            case 1:  acc = pair_sum_rcp<1>(e2, neg_g, p, nIters, tx, wy); break;
            case 2:  acc = pair_sum_rcp<2>(e2, neg_g, p, nIters, tx, wy); break;
            case 3:  acc = pair_sum_rcp<3>(e2, neg_g, p, nIters, tx, wy); break;
            default: acc = pair_sum_rcp<4>(e2, neg_g, p, nIters, tx, wy); break;
        }
    }

    // Block reduction over all 8 warps
    #pragma unroll
    for (int off = 16; off > 0; off >>= 1)
        acc += __shfl_down_sync(0xffffffffu, acc, off);
    if ((tid & 31) == 0) s_warp[tid >> 5] = acc;
    __syncthreads();
    if (tid == 0) {
        float v = 0.0f;
        #pragma unroll
        for (int w = 0; w < NTHREADS / 32; w++) v += s_warp[w];
        float pf = (float)p;
        g_block_loss[b] = 1.0f - v / (pf * pf);
        __threadfence();
        s_is_last = (atomicAdd(&g_done_count, 1u) == (unsigned)(NB - 1));
    }
    __syncthreads();

    // Last block performs the deterministic fixed-tree mean over 4096 losses.
    if (s_is_last) {
        __threadfence();
        __shared__ float s_red[NTHREADS];
        float a = 0.0f;
        #pragma unroll
        for (int i = tid; i < NB; i += NTHREADS)
            a += g_block_loss[i];
        s_red[tid] = a;
        __syncthreads();
        #pragma unroll
        for (int stride = NTHREADS / 2; stride >= 32; stride >>= 1) {
            if (tid < stride) s_red[tid] += s_red[tid + stride];
            __syncthreads();
        }
        if (tid < 32) {
            float v = s_red[tid];
            #pragma unroll
            for (int off = 16; off > 0; off >>= 1)
                v += __shfl_down_sync(0xffffffffu, v, off);
            if (tid == 0) {
                out[0] = v * (1.0f / (float)NB);
                g_done_count = 0;  // reset for next graph replay
            }
        }
    }
}

extern "C" void kernel_launch(void* const* d_in, const int* in_sizes, int n_in,
                              void* d_out, int out_size)
{
    const float* scores_pos = (const float*)d_in[0];
    const float* scores_neg = (const float*)d_in[1];
    const int*   pos_counts = (const int*)d_in[2];
    float* out = (float*)d_out;

    sauc_kernel<<<NB, NTHREADS>>>(scores_pos, scores_neg, pos_counts, out);
}

// round 16
// speedup vs baseline: 1.0412x; 1.0412x over previous
#include <cuda_runtime.h>
#include <cuda_bf16.h>

// Fixed shapes per reference: B=4096 users, P=200 slots, tau=1.0
#define NB 4096
#define PMAX 200
#define PROWS 224
#define NTHREADS 256
#define ROWPAD_T -1.0e30f  // tanh row pad: tanh(-huge) = -1 -> term 0
#define COLPAD_T  1.0e30f  // tanh col pad
#define COLPAD_R  1.0e15f  // rcp col pad: q=1e30 finite, term -> 1 - q*rcp(q) ~ 0

// Scratch (no device allocation allowed -> __device__ globals)
__device__ float g_block_loss[NB];
__device__ unsigned int g_done_count = 0;

__device__ __forceinline__ float fast_tanh(float x) {
    float r;
    asm("tanh.approx.f32 %0, %1;" : "=f"(r) : "f"(x));
    return r;
}
__device__ __forceinline__ float fast_rcp(float x) {
    float r;
    asm("rcp.approx.f32 %0, %1;" : "=f"(r) : "f"(x));
    return r;
}

// ---- Path A (MUFU-heavy): sigmoid(p-n) = 0.5*tanh(ph-nh)+0.5.
//      Warps wy=0..3 -> SMSP 0..3 (one tanh warp per SMSP).
template<int NC>
__device__ __forceinline__ float pair_sum_tanh(const float2* __restrict__ ph2,
                                               const float* __restrict__ neg_g,
                                               int p, int nIters, int tx, int wy)
{
    float nh[NC];
    #pragma unroll
    for (int c = 0; c < NC; c++) {
        int j = c * 32 + tx;
        nh[c] = (j < p) ? (0.5f * neg_g[j]) : COLPAD_T;
    }
    float acc0 = 0.0f, acc1 = 0.0f;
    for (int r = 0; r < nIters; r++) {
        float2 e01 = ph2[r * 8 + wy];        // row pair k = 8r+wy
        const float e0 = e01.x, e1 = e01.y;
        #pragma unroll
        for (int c = 0; c < NC; c++) {
            acc0 = fmaf(0.5f, fast_tanh(e0 - nh[c]), acc0);
            acc1 = fmaf(0.5f, fast_tanh(e1 - nh[c]), acc1);
        }
    }
    return acc0 + acc1 + (float)(nIters * NC);
}

// ---- Path B (fma/issue-heavy, MUFU-light): E=exp(pos), N=exp(neg),
//      e/(e+n0)+e/(e+n1) = 1 + (e^2 - q)*rcp(e^2 + e*m + q).
//      Warps wy=4..7 -> SMSP 0..3 (one rcp warp per SMSP).
template<int NC64>
__device__ __forceinline__ float pair_sum_rcp(const float2* __restrict__ e2,
                                              const float* __restrict__ neg_g,
                                              int p, int nIters, int tx, int wy)
{
    float m[NC64], q[NC64];
    #pragma unroll
    for (int c = 0; c < NC64; c++) {
        int j0 = c * 64 + 2 * tx;
        float n0 = (j0     < p) ? __expf(neg_g[j0])     : COLPAD_R;
        float n1 = (j0 + 1 < p) ? __expf(neg_g[j0 + 1]) : COLPAD_R;
        m[c] = n0 + n1;
        q[c] = n0 * n1;
    }
    float acc0 = 0.0f, acc1 = 0.0f;
    for (int r = 0; r < nIters; r++) {
        float2 e01 = e2[r * 8 + wy];         // row pair k = 8r+wy
        const float e0 = e01.x, e1 = e01.y;
        #pragma unroll
        for (int c = 0; c < NC64; c++) {
            float u0 = e0 + m[c];
            float u1 = e1 + m[c];
            float d0 = fmaf(e0, u0, q[c]);
            float d1 = fmaf(e1, u1, q[c]);
            float g0 = fmaf(e0, e0, -q[c]);
            float g1 = fmaf(e1, e1, -q[c]);
            acc0 = fmaf(g0, fast_rcp(d0), acc0);
            acc1 = fmaf(g1, fast_rcp(d1), acc1);
        }
    }
    return acc0 + acc1 + (float)(2 * nIters * NC64);
}

__global__ __launch_bounds__(NTHREADS, 7) void sauc_kernel(
    const float* __restrict__ scores_pos,
    const float* __restrict__ scores_neg,
    const int* __restrict__ pos_counts,
    float* __restrict__ out)
{
    const int b = blockIdx.x;
    const int tid = threadIdx.x;
    const int tx = tid & 31;
    const int wy = tid >> 5;
    const int p = pos_counts[b];

    __shared__ __align__(8) float s_ph[PROWS];    // pos/2 (tanh rows)
    __shared__ __align__(8) float s_epos[PROWS];  // exp(pos) (rcp rows), 0-pad
    __shared__ float s_warp[NTHREADS / 32];
    __shared__ unsigned int s_is_last;

    if (tid < PROWS) {
        if (tid < p) {
            float v = scores_pos[b * PMAX + tid];
            s_ph[tid]   = 0.5f * v;
            s_epos[tid] = __expf(v);
        } else {
            s_ph[tid]   = ROWPAD_T;
            s_epos[tid] = 0.0f;
        }
    }
    __syncthreads();

    const float* neg_g = scores_neg + b * PMAX;
    const int kpairs = (p + 1) >> 1;           // row pairs
    const int dk = kpairs - wy;
    const int nIters = (dk > 0) ? ((dk + 7) >> 3) : 0;   // warp-uniform
    // rcp warps (wy 4..7) cover classes k ≡ wy (mod 8): their own nIters
    // computed with the same formula — dk uses the true wy, so partition
    // over k is exact across all 8 warps.

    float acc;
    if (wy < 4) {
        // SMSP 0..3 each get exactly one tanh warp
        const float2* ph2 = (const float2*)s_ph;
        const int nc = (p + 31) >> 5;          // 1..7
        switch (nc) {
            case 1:  acc = pair_sum_tanh<1>(ph2, neg_g, p, nIters, tx, wy); break;
            case 2:  acc = pair_sum_tanh<2>(ph2, neg_g, p, nIters, tx, wy); break;
            case 3:  acc = pair_sum_tanh<3>(ph2, neg_g, p, nIters, tx, wy); break;
            case 4:  acc = pair_sum_tanh<4>(ph2, neg_g, p, nIters, tx, wy); break;
            case 5:  acc = pair_sum_tanh<5>(ph2, neg_g, p, nIters, tx, wy); break;
            case 6:  acc = pair_sum_tanh<6>(ph2, neg_g, p, nIters, tx, wy); break;
            default: acc = pair_sum_tanh<7>(ph2, neg_g, p, nIters, tx, wy); break;
        }
    } else {
        // SMSP 0..3 each get exactly one rcp warp
        const float2* e2 = (const float2*)s_epos;
        const int nc64 = (p + 63) >> 6;        // 1..4
        switch (nc64) {
            case 1:  acc = pair_sum_rcp<1>(e2, neg_g, p, nIters, tx, wy); break;
            case 2:  acc = pair_sum_rcp<2>(e2, neg_g, p, nIters, tx, wy); break;
            case 3:  acc = pair_sum_rcp<3>(e2, neg_g, p, nIters, tx, wy); break;
            default: acc = pair_sum_rcp<4>(e2, neg_g, p, nIters, tx, wy); break;
        }
    }

    // Block reduction over all 8 warps
    #pragma unroll
    for (int off = 16; off > 0; off >>= 1)
        acc += __shfl_down_sync(0xffffffffu, acc, off);
    if ((tid & 31) == 0) s_warp[tid >> 5] = acc;
    __syncthreads();
    if (tid == 0) {
        float v = 0.0f;
        #pragma unroll
        for (int w = 0; w < NTHREADS / 32; w++) v += s_warp[w];
        float pf = (float)p;
        g_block_loss[b] = 1.0f - v / (pf * pf);
        __threadfence();
        s_is_last = (atomicAdd(&g_done_count, 1u) == (unsigned)(NB - 1));
    }
    __syncthreads();

    // Last block performs the deterministic fixed-tree mean over 4096 losses.
    if (s_is_last) {
        __threadfence();
        __shared__ float s_red[NTHREADS];
        float a = 0.0f;
        #pragma unroll
        for (int i = tid; i < NB; i += NTHREADS)
            a += g_block_loss[i];
        s_red[tid] = a;
        __syncthreads();
        #pragma unroll
        for (int stride = NTHREADS / 2; stride >= 32; stride >>= 1) {
            if (tid < stride) s_red[tid] += s_red[tid + stride];
            __syncthreads();
        }
        if (tid < 32) {
            float v = s_red[tid];
            #pragma unroll
            for (int off = 16; off > 0; off >>= 1)
                v += __shfl_down_sync(0xffffffffu, v, off);
            if (tid == 0) {
                out[0] = v * (1.0f / (float)NB);
                g_done_count = 0;  // reset for next graph replay
            }
        }
    }
}

extern "C" void kernel_launch(void* const* d_in, const int* in_sizes, int n_in,
                              void* d_out, int out_size)
{
    const float* scores_pos = (const float*)d_in[0];
    const float* scores_neg = (const float*)d_in[1];
    const int*   pos_counts = (const int*)d_in[2];
    float* out = (float*)d_out;

    sauc_kernel<<<NB, NTHREADS>>>(scores_pos, scores_neg, pos_counts, out);
}

// round 17
// speedup vs baseline: 1.0526x; 1.0110x over previous
#include <cuda_runtime.h>
#include <cuda_bf16.h>

// Fixed shapes per reference: B=4096 users, P=200 slots, tau=1.0
#define NB 4096
#define PMAX 200
#define PROWS 224          // row slots exp(pos), zero-padded
#define NTHREADS 256
#define COLPAD_R 1.0e15f   // col pad: q=1e30 finite; pad term -> 1 - q*rcp(q) ~ 0

// Scratch (no device allocation allowed -> __device__ globals)
__device__ float g_block_loss[NB];
__device__ unsigned int g_done_count = 0;

__device__ __forceinline__ float fast_rcp(float x) {
    float r;
    asm("rcp.approx.f32 %0, %1;" : "=f"(r) : "f"(x));
    return r;
}

// 2-pair identity with E=exp(pos), N=exp(neg):
//   e/(e+n0) + e/(e+n1) = 1 + (e^2 - q) * rcp(e^2 + e*m + q), m=n0+n1, q=n0*n1
// Per lane per chunk per row: FADD + FFMA + FFMA + MUFU.RCP(rt8) + FFMA
//   -> 0.078 warp-instr/pair, 0.125 MUFU-cyc/pair (4x less than tanh).
// '+1' baselines analytic (2*nIters*NC64). Pads validated (rel_err 0.0):
//   zero rows (e=0) -> term ~0; COLPAD cols -> term ~0; mixed -> exact single
//   sigmoid by algebraic cancellation.
// Geometry identical to the lean r12 kernel: lane tx owns col pairs
// (64c+2tx, 64c+2tx+1); warp wy handles row-pair classes k = 8r+wy.
template<int NC64>
__device__ __forceinline__ float pair_sum_rcp(const float2* __restrict__ e2,
                                              const float* __restrict__ neg_g,
                                              int p, int nIters, int tx, int wy)
{
    float m[NC64], q[NC64];
    #pragma unroll
    for (int c = 0; c < NC64; c++) {
        int j0 = c * 64 + 2 * tx;
        float n0 = (j0     < p) ? __expf(neg_g[j0])     : COLPAD_R;
        float n1 = (j0 + 1 < p) ? __expf(neg_g[j0 + 1]) : COLPAD_R;
        m[c] = n0 + n1;
        q[c] = n0 * n1;
    }
    float acc0 = 0.0f, acc1 = 0.0f;
    for (int r = 0; r < nIters; r++) {
        float2 e01 = e2[r * 8 + wy];         // rows 2k, 2k+1 (k = 8r+wy)
        const float e0 = e01.x, e1 = e01.y;
        #pragma unroll
        for (int c = 0; c < NC64; c++) {
            float u0 = e0 + m[c];
            float u1 = e1 + m[c];
            float d0 = fmaf(e0, u0, q[c]);
            float d1 = fmaf(e1, u1, q[c]);
            float g0 = fmaf(e0, e0, -q[c]);
            float g1 = fmaf(e1, e1, -q[c]);
            acc0 = fmaf(g0, fast_rcp(d0), acc0);
            acc1 = fmaf(g1, fast_rcp(d1), acc1);
        }
    }
    return acc0 + acc1 + (float)(2 * nIters * NC64);
}

__global__ __launch_bounds__(NTHREADS) void sauc_kernel(
    const float* __restrict__ scores_pos,
    const float* __restrict__ scores_neg,
    const int* __restrict__ pos_counts,
    float* __restrict__ out)
{
    const int b = blockIdx.x;
    const int tid = threadIdx.x;
    const int tx = tid & 31;
    const int wy = tid >> 5;
    const int p = pos_counts[b];

    __shared__ __align__(8) float s_epos[PROWS];  // exp(pos), 0-padded
    __shared__ float s_warp[NTHREADS / 32];
    __shared__ unsigned int s_is_last;

    if (tid < PROWS) {
        s_epos[tid] = (tid < p) ? __expf(scores_pos[b * PMAX + tid]) : 0.0f;
    }
    __syncthreads();

    const float2* e2 = (const float2*)s_epos;
    const float* neg_g = scores_neg + b * PMAX;
    const int nc64 = (p + 63) >> 6;            // 1..4, block-uniform
    const int kpairs = (p + 1) >> 1;           // row pairs
    const int dk = kpairs - wy;
    const int nIters = (dk > 0) ? ((dk + 7) >> 3) : 0;   // warp-uniform

    float acc;
    switch (nc64) {
        case 1:  acc = pair_sum_rcp<1>(e2, neg_g, p, nIters, tx, wy); break;
        case 2:  acc = pair_sum_rcp<2>(e2, neg_g, p, nIters, tx, wy); break;
        case 3:  acc = pair_sum_rcp<3>(e2, neg_g, p, nIters, tx, wy); break;
        default: acc = pair_sum_rcp<4>(e2, neg_g, p, nIters, tx, wy); break;
    }

    // Block reduction
    #pragma unroll
    for (int off = 16; off > 0; off >>= 1)
        acc += __shfl_down_sync(0xffffffffu, acc, off);
    if ((tid & 31) == 0) s_warp[tid >> 5] = acc;
    __syncthreads();
    if (tid == 0) {
        float v = 0.0f;
        #pragma unroll
        for (int w = 0; w < NTHREADS / 32; w++) v += s_warp[w];
        float pf = (float)p;
        g_block_loss[b] = 1.0f - v / (pf * pf);
        __threadfence();
        s_is_last = (atomicAdd(&g_done_count, 1u) == (unsigned)(NB - 1));
    }
    __syncthreads();

    // Last block performs the deterministic fixed-tree mean over 4096 losses.
    if (s_is_last) {
        __threadfence();
        __shared__ float s_red[NTHREADS];
        float a = 0.0f;
        #pragma unroll
        for (int i = tid; i < NB; i += NTHREADS)
            a += g_block_loss[i];
        s_red[tid] = a;
        __syncthreads();
        #pragma unroll
        for (int stride = NTHREADS / 2; stride >= 32; stride >>= 1) {
            if (tid < stride) s_red[tid] += s_red[tid + stride];
            __syncthreads();
        }
        if (tid < 32) {
            float v = s_red[tid];
            #pragma unroll
            for (int off = 16; off > 0; off >>= 1)
                v += __shfl_down_sync(0xffffffffu, v, off);
            if (tid == 0) {
                out[0] = v * (1.0f / (float)NB);
                g_done_count = 0;  // reset for next graph replay
            }
        }
    }
}

extern "C" void kernel_launch(void* const* d_in, const int* in_sizes, int n_in,
                              void* d_out, int out_size)
{
    const float* scores_pos = (const float*)d_in[0];
    const float* scores_neg = (const float*)d_in[1];
    const int*   pos_counts = (const int*)d_in[2];
    float* out = (float*)d_out;

    sauc_kernel<<<NB, NTHREADS>>>(scores_pos, scores_neg, pos_counts, out);
}